// round 9
// baseline (speedup 1.0000x reference)
#include <cuda_runtime.h>

// DynamicRoutingLayer: B=256 N=512 E=64 O=64 K=8, 3 softmax passes.
// cc_t = cc_0 + delta_t[b,k,n];  delta_t[b,k,n] = dot(priors[b,n,:], Vcum_t[b,k,:])
// Pass i prologue recomputes Vcum from per-iteration zpart slots (no tiny kernels).
// Main loop: delta precomputed in smem -> no shfl chain on the hot path.

#define BB 256
#define NN 512
#define EE 64
#define OO 64
#define KK 8
#define NCHUNK 8
#define NPC (NN / NCHUNK)   // 64 n-rows per block

__device__ float g_priors[(size_t)BB * NN * OO];                    // 33.5 MB
__device__ float g_zpart[(size_t)3 * BB * NCHUNK * KK * OO];        // 12.6 MB (slot per iteration)

// ---------------------------------------------------------------------------
// priors[b,n,o] = sum_e emb[b,n,e] * S[e,o].
__global__ __launch_bounds__(256) void gemm_priors_k(const float* __restrict__ emb,
                                                     const float* __restrict__ Sm) {
    __shared__ float sS[64 * 64];      // [e][o]
    __shared__ float sE[64 * 65];      // [r][e] padded
    const int tid = threadIdx.x;
    const size_t rowBase = (size_t)blockIdx.x * 64;   // flattened (b*N + n)

    for (int i = tid; i < 4096; i += 256) sS[i] = Sm[i];
    for (int i = tid; i < 4096; i += 256) sE[(i >> 6) * 65 + (i & 63)] = emb[rowBase * EE + i];
    __syncthreads();

    const int tc = tid & 15, tr = tid >> 4;
    const int r0 = tr * 4, o0 = tc * 4;
    float a[4][4];
#pragma unroll
    for (int i = 0; i < 4; i++)
#pragma unroll
        for (int j = 0; j < 4; j++) a[i][j] = 0.0f;

#pragma unroll 8
    for (int e = 0; e < 64; e++) {
        float4 sv = *(const float4*)(sS + e * 64 + o0);
#pragma unroll
        for (int i = 0; i < 4; i++) {
            float av = sE[(r0 + i) * 65 + e];
            a[i][0] += av * sv.x;
            a[i][1] += av * sv.y;
            a[i][2] += av * sv.z;
            a[i][3] += av * sv.w;
        }
    }
#pragma unroll
    for (int i = 0; i < 4; i++) {
        float4 v = make_float4(a[i][0], a[i][1], a[i][2], a[i][3]);
        *(float4*)(g_priors + (rowBase + r0 + i) * OO + o0) = v;
    }
}

// ---------------------------------------------------------------------------
// Routing pass ITER (0,1,2).
// Prologue: Vcum = sum_{i<ITER} squash(sum_chunks zpart[i][b]).  (redundant per block, L2-hit)
// Phase 1: stage priors chunk in smem; delta[n][k] = dot(p[n,:], Vcum[k,:]) via warp shfl.
// Main:    z-partials with per-thread softmax over K; delta read as smem broadcast.
// __launch_bounds__(256,3): pin >=3 blocks/SM (24 warps) -- latency hiding is the
// binding constraint identified in the R3 measurement.
template <int ITER>
__global__ __launch_bounds__(256, 3) void routing_pass_k(const float* __restrict__ cc0) {
    __shared__ float sP[NPC * OO];       // 16 KB priors chunk [n][o]
    __shared__ float sV[KK * 68];        // Vcum, padded rows
    __shared__ float sDZ[576];           // delta[n*8+k] (512) / prologue z scratch (8*68=544)
    __shared__ float sred[8 * KK * OO];  // 16 KB cross-warp partials

    const int b = blockIdx.y;
    const int chunk = blockIdx.x;
    const int tid = threadIdx.x;
    const int warp = tid >> 5;
    const int lane = tid & 31;

    // stage priors chunk (coalesced float4)
    const float* pbase = g_priors + ((size_t)b * NN + chunk * NPC) * OO;
    for (int i = tid; i < NPC * OO / 4; i += 256)
        ((float4*)sP)[i] = ((const float4*)pbase)[i];

    for (int i = tid; i < KK * 68; i += 256) sV[i] = 0.0f;
    __syncthreads();

    // ---- prologue: rebuild Vcum from previous iterations' zpart ----
#pragma unroll
    for (int it = 0; it < ITER; ++it) {
        for (int idx = tid; idx < KK * OO; idx += 256) {
            const int k = idx >> 6, o = idx & 63;
            const float* zp = g_zpart + (((size_t)it * BB + b) * NCHUNK) * KK * OO + k * OO + o;
            float z = 0.0f;
#pragma unroll
            for (int c = 0; c < NCHUNK; c++) z += zp[(size_t)c * KK * OO];
            sDZ[k * 68 + o] = z;
        }
        __syncthreads();
        {   // warp w squashes capsule k = w
            const int k = warp;
            const float z0 = sDZ[k * 68 + 2 * lane];
            const float z1 = sDZ[k * 68 + 2 * lane + 1];
            float sq = z0 * z0 + z1 * z1;
#pragma unroll
            for (int off = 16; off > 0; off >>= 1) sq += __shfl_xor_sync(0xffffffffu, sq, off);
            const float f = (sq / (1.0f + sq)) * rsqrtf(sq + 1e-9f);
            sV[k * 68 + 2 * lane] += f * z0;
            sV[k * 68 + 2 * lane + 1] += f * z1;
        }
        __syncthreads();
    }

    // ---- phase 1: delta[n][k] = dot(p[n,:], Vcum[k,:]) ----
    {
        float vc0[KK], vc1[KK];
#pragma unroll
        for (int k = 0; k < KK; k++) {
            vc0[k] = sV[k * 68 + 2 * lane];
            vc1[k] = sV[k * 68 + 2 * lane + 1];
        }
        for (int n = warp; n < NPC; n += 8) {
            const float2 p = *(const float2*)(sP + n * OO + 2 * lane);
            float d[KK];
#pragma unroll
            for (int k = 0; k < KK; k++) d[k] = p.x * vc0[k] + p.y * vc1[k];
#pragma unroll
            for (int off = 16; off > 0; off >>= 1) {
#pragma unroll
                for (int k = 0; k < KK; k++) d[k] += __shfl_xor_sync(0xffffffffu, d[k], off);
            }
            if (lane == 0) {
#pragma unroll
                for (int k = 0; k < KK; k++) sDZ[n * 8 + k] = d[k];
            }
        }
    }
    __syncthreads();

    // ---- main loop: softmax over K per (n,o), accumulate z partials ----
    float acc0[KK], acc1[KK];
#pragma unroll
    for (int k = 0; k < KK; k++) { acc0[k] = 0.0f; acc1[k] = 0.0f; }

    const float* ccb = cc0 + (size_t)b * KK * NN * OO + (size_t)(chunk * NPC) * OO + 2 * lane;

    for (int nn = warp; nn < NPC; nn += 8) {
        const float* cp = ccb + (size_t)nn * OO;
        float2 c[KK];
#pragma unroll
        for (int k = 0; k < KK; k++) c[k] = *(const float2*)(cp + (size_t)k * NN * OO);
        const float2 p = *(const float2*)(sP + nn * OO + 2 * lane);

        float s0[KK], s1[KK];
#pragma unroll
        for (int k = 0; k < KK; k++) {
            const float dk = sDZ[nn * 8 + k];
            s0[k] = c[k].x + dk;
            s1[k] = c[k].y + dk;
        }
        float m0 = s0[0], m1 = s1[0];
#pragma unroll
        for (int k = 1; k < KK; k++) { m0 = fmaxf(m0, s0[k]); m1 = fmaxf(m1, s1[k]); }
        float sum0 = 0.0f, sum1 = 0.0f;
#pragma unroll
        for (int k = 0; k < KK; k++) {
            s0[k] = __expf(s0[k] - m0); sum0 += s0[k];
            s1[k] = __expf(s1[k] - m1); sum1 += s1[k];
        }
        const float w0 = p.x * __frcp_rn(sum0);
        const float w1 = p.y * __frcp_rn(sum1);
#pragma unroll
        for (int k = 0; k < KK; k++) {
            acc0[k] += s0[k] * w0;
            acc1[k] += s1[k] * w1;
        }
    }

    // deterministic cross-warp reduction -> zpart slot ITER
#pragma unroll
    for (int k = 0; k < KK; k++) {
        sred[warp * KK * OO + k * OO + 2 * lane] = acc0[k];
        sred[warp * KK * OO + k * OO + 2 * lane + 1] = acc1[k];
    }
    __syncthreads();
    float* zout = g_zpart + (((size_t)ITER * BB + b) * NCHUNK + chunk) * KK * OO;
#pragma unroll 2
    for (int s = tid; s < KK * OO; s += 256) {
        float t = 0.0f;
#pragma unroll
        for (int w = 0; w < 8; w++) t += sred[w * KK * OO + s];
        zout[s] = t;
    }
}

// ---------------------------------------------------------------------------
// Final output: squash(z) from pass-2 zpart. One block per b, warp w = capsule w.
__global__ __launch_bounds__(256) void squash_out_k(float* __restrict__ out) {
    const int b = blockIdx.x;
    const int warp = threadIdx.x >> 5, lane = threadIdx.x & 31;
    const int k = warp;
    float z0 = 0.0f, z1 = 0.0f;
#pragma unroll
    for (int c = 0; c < NCHUNK; c++) {
        const float* zp = g_zpart + (((size_t)2 * BB + b) * NCHUNK + c) * KK * OO + k * OO;
        z0 += zp[2 * lane];
        z1 += zp[2 * lane + 1];
    }
    float sq = z0 * z0 + z1 * z1;
#pragma unroll
    for (int off = 16; off > 0; off >>= 1) sq += __shfl_xor_sync(0xffffffffu, sq, off);
    const float f = (sq / (1.0f + sq)) * rsqrtf(sq + 1e-9f);
    out[((size_t)b * KK + k) * OO + 2 * lane] = f * z0;
    out[((size_t)b * KK + k) * OO + 2 * lane + 1] = f * z1;
}

// ---------------------------------------------------------------------------
extern "C" void kernel_launch(void* const* d_in, const int* in_sizes, int n_in,
                              void* d_out, int out_size) {
    const float* emb = (const float*)d_in[0];   // (B,N,E) fp32
    const float* Sm  = (const float*)d_in[1];   // (E,O)   fp32
    const float* cc  = (const float*)d_in[2];   // (B,K,N,O) fp32
    float* out = (float*)d_out;                 // (B,K,O) fp32

    gemm_priors_k<<<BB * NN / 64, 256>>>(emb, Sm);

    dim3 rg(NCHUNK, BB);
    routing_pass_k<0><<<rg, 256>>>(cc);
    routing_pass_k<1><<<rg, 256>>>(cc);
    routing_pass_k<2><<<rg, 256>>>(cc);
    squash_out_k<<<BB, 256>>>(out);
}